// round 2
// baseline (speedup 1.0000x reference)
#include <cuda_runtime.h>
#include <stdint.h>

#define HH 2048
#define WW 2048
#define NPIX (HH * WW)

#define TW 32                    // tile width
#define TH 16                    // tile height
#define SW (TW + 2)              // 34 (halo)
#define SH (TH + 2)              // 18 (halo)
#define NSLOT (SW * SH)          // 612

__device__ float g_scratch[NPIX];

// ---------------------------------------------------------------------------
// Threefry-2x32, 20 rounds — exact transcription of jax._src.prng
// ---------------------------------------------------------------------------
__host__ __device__ __forceinline__ uint32_t rotl32(uint32_t v, uint32_t r) {
#ifdef __CUDA_ARCH__
    return __funnelshift_l(v, v, r);
#else
    return (v << r) | (v >> (32u - r));
#endif
}

__host__ __device__ __forceinline__ void tf2x32(uint32_t k0, uint32_t k1,
                                                uint32_t x0, uint32_t x1,
                                                uint32_t& o0, uint32_t& o1) {
    uint32_t ks2 = k0 ^ k1 ^ 0x1BD11BDAu;
    x0 += k0; x1 += k1;
#define TF_R(r) { x0 += x1; x1 = rotl32(x1, r); x1 ^= x0; }
    TF_R(13u) TF_R(15u) TF_R(26u) TF_R(6u)
    x0 += k1;  x1 += ks2 + 1u;
    TF_R(17u) TF_R(29u) TF_R(16u) TF_R(24u)
    x0 += ks2; x1 += k0 + 2u;
    TF_R(13u) TF_R(15u) TF_R(26u) TF_R(6u)
    x0 += k0;  x1 += k1 + 3u;
    TF_R(17u) TF_R(29u) TF_R(16u) TF_R(24u)
    x0 += k1;  x1 += ks2 + 4u;
    TF_R(13u) TF_R(15u) TF_R(26u) TF_R(6u)
    x0 += ks2; x1 += k0 + 5u;
#undef TF_R
    o0 = x0; o1 = x1;
}

// Partitionable-mode random bits for flat index p (p < 2^32):
//   counter = (0, p); bits = o0 ^ o1
__device__ __forceinline__ uint32_t pbits(uint32_t k0, uint32_t k1, uint32_t p) {
    uint32_t o0, o1;
    tf2x32(k0, k1, 0u, p, o0, o1);
    return o0 ^ o1;
}

// uniform in [0,1): bitcast((bits>>9)|0x3f800000) - 1.0f  (exact JAX formula)
__device__ __forceinline__ float bits_to_uniform(uint32_t bits) {
    return __fsub_rn(__uint_as_float((bits >> 9) | 0x3f800000u), 1.0f);
}

// ---------------------------------------------------------------------------
// x0 = seed * habitat * goodness
// ---------------------------------------------------------------------------
__global__ void init_kernel(const float* __restrict__ seed,
                            const float* __restrict__ hab,
                            const float* __restrict__ good,
                            float* __restrict__ xout) {
    int idx = blockIdx.x * blockDim.x + threadIdx.x;
    if (idx < NPIX)
        xout[idx] = __fmul_rn(__fmul_rn(seed[idx], hab[idx]), good[idx]);
}

// ---------------------------------------------------------------------------
// One spread step, fused:
//   y1 = x * (0.9999 + 1e-4*u1); y2 = maxpool3x3(y1); y3 = y2*(u2>0.5);
//   y4 = y3*goodness; x' = max(y4*((y4-x) > 0.05), x)
// Each block: one TW x TH tile; halo staged in smem with per-pixel noise.
// ---------------------------------------------------------------------------
__global__ __launch_bounds__(256)
void step_kernel(const float* __restrict__ xin, float* __restrict__ xout,
                 const float* __restrict__ good,
                 uint32_t k1a, uint32_t k1b, uint32_t k2a, uint32_t k2b) {
    __shared__ float ys[SH][SW];   // noised x (maxpool operand)
    __shared__ float xs[SH][SW];   // raw x (for delta / max)

    const int tid = threadIdx.x;
    const int c0 = blockIdx.x * TW;
    const int r0 = blockIdx.y * TH;

    // ---- fill phase: noised tile with halo ----
    #pragma unroll
    for (int k = 0; k < 3; k++) {
        int s = tid + k * 256;
        bool sv = s < NSLOT;
        int ss = sv ? s : 0;
        int j = ss / SW;
        int i = ss % SW;
        int r = r0 - 1 + j;
        int c = c0 - 1 + i;
        bool ok = sv && (r >= 0) && (r < HH) && (c >= 0) && (c < WW);
        float x = ok ? xin[r * WW + c] : 0.0f;
        float y1 = 0.0f;
        if (__ballot_sync(0xffffffffu, x > 0.0f)) {
            uint32_t p = ok ? (uint32_t)(r * WW + c) : 0u;
            float u = bits_to_uniform(pbits(k1a, k1b, p));
            float f = __fadd_rn(0.9999f, __fmul_rn(1e-4f, u));
            y1 = __fmul_rn(x, f);
        }
        if (sv) { ys[j][i] = y1; xs[j][i] = x; }
    }
    __syncthreads();

    // ---- compute phase: 2 output pixels per thread ----
    const int tx = tid & 31;
    const int ty = tid >> 5;                     // 0..7
    #pragma unroll
    for (int k = 0; k < 2; k++) {
        int jj = 1 + ty + k * 8;                 // 1..16
        int ii = 1 + tx;                         // 1..32
        float m = ys[jj - 1][ii - 1];
        m = fmaxf(m, ys[jj - 1][ii    ]);
        m = fmaxf(m, ys[jj - 1][ii + 1]);
        m = fmaxf(m, ys[jj    ][ii - 1]);
        m = fmaxf(m, ys[jj    ][ii    ]);
        m = fmaxf(m, ys[jj    ][ii + 1]);
        m = fmaxf(m, ys[jj + 1][ii - 1]);
        m = fmaxf(m, ys[jj + 1][ii    ]);
        m = fmaxf(m, ys[jj + 1][ii + 1]);

        float xx = xs[jj][ii];
        int r = r0 + jj - 1;
        int c = c0 + ii - 1;
        uint32_t p = (uint32_t)(r * WW + c);

        float y4 = 0.0f;
        if (__ballot_sync(0xffffffffu, m > 0.0f)) {
            uint32_t bits = pbits(k2a, k2b, p);
            // u > 0.5 strictly <=> (bits>>9) > 0x400000 (u == 0.5 exactly fails)
            bool coin = ((bits >> 9) > 0x400000u);
            if (coin && m > 0.0f) y4 = __fmul_rn(m, good[p]);
        }
        float d  = __fsub_rn(y4, xx);
        float y5 = (d > 0.05f) ? y4 : 0.0f;
        xout[p] = fmaxf(y5, xx);
    }
}

// ---------------------------------------------------------------------------
// Host: per-iteration key schedule (fold_in + fold-like split), ping-pong.
// Partitionable split: k_i = cipher(f, (0, i)) -> (o0, o1) is the new key.
// ---------------------------------------------------------------------------
extern "C" void kernel_launch(void* const* d_in, const int* in_sizes, int n_in,
                              void* d_out, int out_size) {
    const float* seed = (const float*)d_in[0];
    const float* hab  = (const float*)d_in[1];
    const float* good = (const float*)d_in[2];
    float* xout = (float*)d_out;

    float* scratch = nullptr;
    cudaGetSymbolAddress((void**)&scratch, g_scratch);

    init_kernel<<<(NPIX + 255) / 256, 256>>>(seed, hab, good, xout);

    dim3 grid(WW / TW, HH / TH);   // 64 x 128
    for (int i = 0; i < 100; i++) {
        // fold_in(key(42)=(0,42), i) = cipher((0,42), (0,i))  [mode-independent]
        uint32_t f0, f1;
        tf2x32(0u, 42u, 0u, (uint32_t)i, f0, f1);
        // partitionable split: k1 = cipher(f,(0,0)), k2 = cipher(f,(0,1))
        uint32_t k1a, k1b, k2a, k2b;
        tf2x32(f0, f1, 0u, 0u, k1a, k1b);
        tf2x32(f0, f1, 0u, 1u, k2a, k2b);

        const float* xin = (i & 1) ? scratch : xout;
        float*       xo  = (i & 1) ? xout    : scratch;
        step_kernel<<<grid, 256>>>(xin, xo, good, k1a, k1b, k2a, k2b);
    }
    // i = 99 (odd) wrote into xout -> final state lands in d_out
}

// round 3
// speedup vs baseline: 1.8041x; 1.8041x over previous
#include <cuda_runtime.h>
#include <stdint.h>

#define HH 2048
#define WW 2048
#define NPIX (HH * WW)

#define TW 32                    // tile width
#define TH 16                    // tile height
#define SW (TW + 2)              // 34 (halo)
#define SH (TH + 2)              // 18 (halo)
#define NSLOT (SW * SH)          // 612

#define NBX (WW / TW)            // 64
#define NBY (HH / TH)            // 128
#define NB  (NBX * NBY)          // 8192

__device__ float g_scratch[NPIX];
__device__ int   g_changed[2][NB];
__device__ int   g_possible[NB];

// ---------------------------------------------------------------------------
// Threefry-2x32, 20 rounds — exact transcription of jax._src.prng
// ---------------------------------------------------------------------------
__host__ __device__ __forceinline__ uint32_t rotl32(uint32_t v, uint32_t r) {
#ifdef __CUDA_ARCH__
    return __funnelshift_l(v, v, r);
#else
    return (v << r) | (v >> (32u - r));
#endif
}

__host__ __device__ __forceinline__ void tf2x32(uint32_t k0, uint32_t k1,
                                                uint32_t x0, uint32_t x1,
                                                uint32_t& o0, uint32_t& o1) {
    uint32_t ks2 = k0 ^ k1 ^ 0x1BD11BDAu;
    x0 += k0; x1 += k1;
#define TF_R(r) { x0 += x1; x1 = rotl32(x1, r); x1 ^= x0; }
    TF_R(13u) TF_R(15u) TF_R(26u) TF_R(6u)
    x0 += k1;  x1 += ks2 + 1u;
    TF_R(17u) TF_R(29u) TF_R(16u) TF_R(24u)
    x0 += ks2; x1 += k0 + 2u;
    TF_R(13u) TF_R(15u) TF_R(26u) TF_R(6u)
    x0 += k0;  x1 += k1 + 3u;
    TF_R(17u) TF_R(29u) TF_R(16u) TF_R(24u)
    x0 += k1;  x1 += ks2 + 4u;
    TF_R(13u) TF_R(15u) TF_R(26u) TF_R(6u)
    x0 += ks2; x1 += k0 + 5u;
#undef TF_R
    o0 = x0; o1 = x1;
}

// Partitionable-mode random bits for flat index p: counter=(0,p); bits=o0^o1
__device__ __forceinline__ uint32_t pbits(uint32_t k0, uint32_t k1, uint32_t p) {
    uint32_t o0, o1;
    tf2x32(k0, k1, 0u, p, o0, o1);
    return o0 ^ o1;
}

__device__ __forceinline__ float bits_to_uniform(uint32_t bits) {
    return __fsub_rn(__uint_as_float((bits >> 9) | 0x3f800000u), 1.0f);
}

// ---------------------------------------------------------------------------
// x0 = seed * habitat * goodness  (+ reset tile flags)
// ---------------------------------------------------------------------------
__global__ void init_kernel(const float* __restrict__ seed,
                            const float* __restrict__ hab,
                            const float* __restrict__ good,
                            float* __restrict__ xout) {
    int idx = blockIdx.x * blockDim.x + threadIdx.x;
    if (idx < NPIX)
        xout[idx] = __fmul_rn(__fmul_rn(seed[idx], hab[idx]), good[idx]);
    if (idx < NB) {
        g_changed[1][idx] = 1;   // iter 0 reads parity 1 -> force full compute
        g_changed[0][idx] = 0;
        g_possible[idx]   = 0;
    }
}

// ---------------------------------------------------------------------------
// One spread step with 3-level skipping (see header comment in response).
// ---------------------------------------------------------------------------
__global__ __launch_bounds__(256)
void step_kernel(const float* __restrict__ xin, float* __restrict__ xout,
                 const float* __restrict__ good,
                 uint32_t k1a, uint32_t k1b, uint32_t k2a, uint32_t k2b,
                 int prevPar, int curPar) {
    __shared__ float xs[SH][SW];     // raw x (tile + halo)
    __shared__ float ys[SH][SW];     // noised x (maxpool operand)
    __shared__ unsigned s_posmask[TH];
    __shared__ int s_need, s_selfchg;

    const int tid = threadIdx.x;
    const int bx = blockIdx.x, by = blockIdx.y;
    const int b  = by * NBX + bx;
    const int c0 = bx * TW;
    const int r0 = by * TH;

    // ==== level 1: tile-level temporal skip via flags ====
    if (tid == 0) { s_need = 0; s_selfchg = 0; }
    __syncthreads();
    if (tid < 9) {
        int dy = tid / 3 - 1, dx = tid % 3 - 1;
        int ny = by + dy, nx = bx + dx;
        int ch = 0;
        if (ny >= 0 && ny < NBY && nx >= 0 && nx < NBX)
            ch = g_changed[prevPar][ny * NBX + nx];
        if (ch) {
            s_need = 1;
            if (tid == 4) s_selfchg = 1;
        }
    } else if (tid == 9) {
        if (g_possible[b]) s_need = 1;
    }
    __syncthreads();
    if (!s_need) {
        // possible_prev==false and no neighbor changed -> x unchanged here,
        // and out buffer (x_{i-1}) already equals x_i on this tile.
        if (tid == 0) g_changed[curPar][b] = 0;
        return;
    }

    // ==== load raw x tile + halo ====
    #pragma unroll
    for (int k = 0; k < 3; k++) {
        int s = tid + k * 256;
        if (s < NSLOT) {
            int j = s / SW, i = s % SW;
            int r = r0 - 1 + j, c = c0 - 1 + i;
            bool ok = (r >= 0) && (r < HH) && (c >= 0) && (c < WW);
            xs[j][i] = ok ? xin[r * WW + c] : 0.0f;
        }
    }
    __syncthreads();

    // ==== per-cell "possible" upper bound: fsub(fmul(max3x3(x),good),x) > 0.05 ====
    const int tx = tid & 31;
    const int ty = tid >> 5;                     // 0..7
    float xx[2], gd[2];
    bool  pos[2];
    #pragma unroll
    for (int k = 0; k < 2; k++) {
        int jj = 1 + ty + k * 8, ii = 1 + tx;
        float M = xs[jj - 1][ii - 1];
        M = fmaxf(M, xs[jj - 1][ii    ]);
        M = fmaxf(M, xs[jj - 1][ii + 1]);
        M = fmaxf(M, xs[jj    ][ii - 1]);
        M = fmaxf(M, xs[jj    ][ii    ]);
        M = fmaxf(M, xs[jj    ][ii + 1]);
        M = fmaxf(M, xs[jj + 1][ii - 1]);
        M = fmaxf(M, xs[jj + 1][ii    ]);
        M = fmaxf(M, xs[jj + 1][ii + 1]);
        xx[k] = xs[jj][ii];
        int r = r0 + jj - 1, c = c0 + ii - 1;
        gd[k] = good[r * WW + c];
        pos[k] = __fsub_rn(__fmul_rn(M, gd[k]), xx[k]) > 0.05f;
        unsigned rowmask = __ballot_sync(0xffffffffu, pos[k]);
        if (tx == 0) s_posmask[ty + k * 8] = rowmask;
    }
    int any = __syncthreads_or((pos[0] || pos[1]) ? 1 : 0);

    if (!any) {
        // ==== level 2: no update possible anywhere -> copy (if buffers differ) ====
        if (s_selfchg) {
            #pragma unroll
            for (int k = 0; k < 2; k++) {
                int jj = 1 + ty + k * 8, ii = 1 + tx;
                int r = r0 + jj - 1, c = c0 + ii - 1;
                xout[r * WW + c] = xx[k];
            }
        }
        if (tid == 0) { g_changed[curPar][b] = 0; g_possible[b] = 0; }
        return;
    }

    // ==== fill noised tile, cipher gated on pos-mask dilated by 1 px ====
    #pragma unroll
    for (int k = 0; k < 3; k++) {
        int s = tid + k * 256;
        bool sv = s < NSLOT;
        int ss = sv ? s : 0;
        int j = ss / SW, i = ss % SW;
        float x = sv ? xs[j][i] : 0.0f;
        unsigned rm = 0;
        #pragma unroll
        for (int dr = 0; dr < 3; dr++) {
            int cr = j - 2 + dr;
            if (cr >= 0 && cr < TH) rm |= s_posmask[cr];
        }
        unsigned long long rm2 = ((unsigned long long)rm) << 2;
        bool need = (((rm2 >> i) & 7ull) != 0ull) && (x > 0.0f);
        float y1 = 0.0f;
        if (__ballot_sync(0xffffffffu, need)) {
            int r = r0 - 1 + j, c = c0 - 1 + i;
            // clamp for inactive lanes only; active lanes are in-bounds (x>0)
            uint32_t p = (uint32_t)(min(max(r, 0), HH - 1) * WW + min(max(c, 0), WW - 1));
            float u = bits_to_uniform(pbits(k1a, k1b, p));
            float f = __fadd_rn(0.9999f, __fmul_rn(1e-4f, u));
            y1 = __fmul_rn(x, f);
        }
        if (sv) ys[j][i] = y1;
    }
    __syncthreads();

    // ==== maxpool + coin (cipher gated on pos) + write ====
    int chg = 0;
    #pragma unroll
    for (int k = 0; k < 2; k++) {
        int jj = 1 + ty + k * 8, ii = 1 + tx;
        float m = ys[jj - 1][ii - 1];
        m = fmaxf(m, ys[jj - 1][ii    ]);
        m = fmaxf(m, ys[jj - 1][ii + 1]);
        m = fmaxf(m, ys[jj    ][ii - 1]);
        m = fmaxf(m, ys[jj    ][ii    ]);
        m = fmaxf(m, ys[jj    ][ii + 1]);
        m = fmaxf(m, ys[jj + 1][ii - 1]);
        m = fmaxf(m, ys[jj + 1][ii    ]);
        m = fmaxf(m, ys[jj + 1][ii + 1]);

        int r = r0 + jj - 1, c = c0 + ii - 1;
        uint32_t p = (uint32_t)(r * WW + c);
        float y4 = 0.0f;
        if (__ballot_sync(0xffffffffu, pos[k])) {
            uint32_t bits = pbits(k2a, k2b, p);
            bool coin = ((bits >> 9) > 0x400000u);   // u > 0.5 strictly
            if (coin && m > 0.0f) y4 = __fmul_rn(m, gd[k]);
        }
        // for !pos lanes: delta <= UB <= 0.05 -> threshold false automatically
        float d  = __fsub_rn(y4, xx[k]);
        float y5 = (d > 0.05f) ? y4 : 0.0f;
        float out = fmaxf(y5, xx[k]);
        xout[p] = out;
        chg |= (out != xx[k]) ? 1 : 0;
    }
    int anychg = __syncthreads_or(chg);
    if (tid == 0) { g_changed[curPar][b] = anychg; g_possible[b] = 1; }
}

// ---------------------------------------------------------------------------
// Host: per-iteration key schedule (fold_in + partitionable split), ping-pong.
// ---------------------------------------------------------------------------
extern "C" void kernel_launch(void* const* d_in, const int* in_sizes, int n_in,
                              void* d_out, int out_size) {
    const float* seed = (const float*)d_in[0];
    const float* hab  = (const float*)d_in[1];
    const float* good = (const float*)d_in[2];
    float* xout = (float*)d_out;

    float* scratch = nullptr;
    cudaGetSymbolAddress((void**)&scratch, g_scratch);

    init_kernel<<<(NPIX + 255) / 256, 256>>>(seed, hab, good, xout);

    dim3 grid(NBX, NBY);   // 64 x 128
    for (int i = 0; i < 100; i++) {
        // fold_in(key(42)=(0,42), i) = cipher((0,42), (0,i))
        uint32_t f0, f1;
        tf2x32(0u, 42u, 0u, (uint32_t)i, f0, f1);
        // partitionable split: k1 = cipher(f,(0,0)), k2 = cipher(f,(0,1))
        uint32_t k1a, k1b, k2a, k2b;
        tf2x32(f0, f1, 0u, 0u, k1a, k1b);
        tf2x32(f0, f1, 0u, 1u, k2a, k2b);

        const float* xin = (i & 1) ? scratch : xout;
        float*       xo  = (i & 1) ? xout    : scratch;
        step_kernel<<<grid, 256>>>(xin, xo, good, k1a, k1b, k2a, k2b,
                                   (i + 1) & 1, i & 1);
    }
    // i = 99 (odd) wrote into xout -> final state lands in d_out
}

// round 4
// speedup vs baseline: 2.0555x; 1.1393x over previous
#include <cuda_runtime.h>
#include <stdint.h>

#define HH 2048
#define WW 2048
#define NPIX (HH * WW)

#define TW 32                    // tile width
#define TH 16                    // tile height
#define SW (TW + 2)              // 34 (halo)
#define SH (TH + 2)              // 18 (halo)
#define NSLOT (SW * SH)          // 612

#define NBX (WW / TW)            // 64
#define NBY (HH / TH)            // 128
#define NB  (NBX * NBY)          // 8192

#define STEP_GRID 2048

__device__ float g_scratch[NPIX];
__device__ int   g_changed[2][NB];
__device__ int   g_possible[NB];
__device__ int   g_worklist[2][NB];
__device__ int   g_nwork[2];

// ---------------------------------------------------------------------------
// Threefry-2x32, 20 rounds — exact transcription of jax._src.prng
// ---------------------------------------------------------------------------
__host__ __device__ __forceinline__ uint32_t rotl32(uint32_t v, uint32_t r) {
#ifdef __CUDA_ARCH__
    return __funnelshift_l(v, v, r);
#else
    return (v << r) | (v >> (32u - r));
#endif
}

__host__ __device__ __forceinline__ void tf2x32(uint32_t k0, uint32_t k1,
                                                uint32_t x0, uint32_t x1,
                                                uint32_t& o0, uint32_t& o1) {
    uint32_t ks2 = k0 ^ k1 ^ 0x1BD11BDAu;
    x0 += k0; x1 += k1;
#define TF_R(r) { x0 += x1; x1 = rotl32(x1, r); x1 ^= x0; }
    TF_R(13u) TF_R(15u) TF_R(26u) TF_R(6u)
    x0 += k1;  x1 += ks2 + 1u;
    TF_R(17u) TF_R(29u) TF_R(16u) TF_R(24u)
    x0 += ks2; x1 += k0 + 2u;
    TF_R(13u) TF_R(15u) TF_R(26u) TF_R(6u)
    x0 += k0;  x1 += k1 + 3u;
    TF_R(17u) TF_R(29u) TF_R(16u) TF_R(24u)
    x0 += k1;  x1 += ks2 + 4u;
    TF_R(13u) TF_R(15u) TF_R(26u) TF_R(6u)
    x0 += ks2; x1 += k0 + 5u;
#undef TF_R
    o0 = x0; o1 = x1;
}

// Partitionable-mode random bits for flat index p: counter=(0,p); bits=o0^o1
__device__ __forceinline__ uint32_t pbits(uint32_t k0, uint32_t k1, uint32_t p) {
    uint32_t o0, o1;
    tf2x32(k0, k1, 0u, p, o0, o1);
    return o0 ^ o1;
}

__device__ __forceinline__ float bits_to_uniform(uint32_t bits) {
    return __fsub_rn(__uint_as_float((bits >> 9) | 0x3f800000u), 1.0f);
}

// ---------------------------------------------------------------------------
// x0 = seed * habitat * goodness  (+ reset flags/counters)
// ---------------------------------------------------------------------------
__global__ void init_kernel(const float* __restrict__ seed,
                            const float* __restrict__ hab,
                            const float* __restrict__ good,
                            float* __restrict__ xout) {
    int idx = blockIdx.x * blockDim.x + threadIdx.x;
    if (idx < NPIX)
        xout[idx] = __fmul_rn(__fmul_rn(seed[idx], hab[idx]), good[idx]);
    if (idx < NB) {
        g_changed[1][idx] = 1;   // iter 0 reads parity 1 -> force full compute
        g_changed[0][idx] = 0;
        g_possible[idx]   = 0;
    }
    if (idx == 0) { g_nwork[0] = 0; g_nwork[1] = 0; }
}

// ---------------------------------------------------------------------------
// Per-step worklist build: need = possible | dilate3x3(changed_prev).
// Also pre-zeroes changed[cur] and the next parity's counter.
// One thread per tile; warp-aggregated compaction.
// ---------------------------------------------------------------------------
__global__ __launch_bounds__(256)
void flag_kernel(int prevPar, int curPar) {
    int t = blockIdx.x * blockDim.x + threadIdx.x;   // tile id, NB = 8192 exact
    int by = t / NBX, bx = t % NBX;

    int need = g_possible[t];
    #pragma unroll
    for (int dy = -1; dy <= 1; dy++) {
        #pragma unroll
        for (int dx = -1; dx <= 1; dx++) {
            int ny = by + dy, nx = bx + dx;
            if (ny >= 0 && ny < NBY && nx >= 0 && nx < NBX)
                need |= g_changed[prevPar][ny * NBX + nx];
        }
    }
    g_changed[curPar][t] = 0;
    if (t == 0) g_nwork[prevPar] = 0;   // counter for next step's parity

    unsigned m = __ballot_sync(0xffffffffu, need != 0);
    int base = 0;
    if ((threadIdx.x & 31) == 0 && m)
        base = atomicAdd(&g_nwork[curPar], __popc(m));
    base = __shfl_sync(0xffffffffu, base, 0);
    if (need) {
        int rank = __popc(m & ((1u << (threadIdx.x & 31)) - 1u));
        g_worklist[curPar][base + rank] = t;
    }
}

// ---------------------------------------------------------------------------
// One spread step over the compact worklist (grid-stride).
//   y1 = x * (0.9999 + 1e-4*u1); y2 = maxpool3x3(y1); y3 = y2*(u2>0.5);
//   y4 = y3*goodness; x' = max(y4*((y4-x) > 0.05), x)
// Cell-level skipping: "possible" iff fsub(fmul(max3x3(x),good),x) > 0.05
// (exact float upper bound since noise factor <= 1.0f).
// ---------------------------------------------------------------------------
__global__ __launch_bounds__(256)
void step_kernel(const float* __restrict__ xin, float* __restrict__ xout,
                 const float* __restrict__ good,
                 uint32_t k1a, uint32_t k1b, uint32_t k2a, uint32_t k2b,
                 int prevPar, int curPar) {
    __shared__ float xs[SH][SW];     // raw x (tile + halo)
    __shared__ float ys[SH][SW];     // noised x (maxpool operand)
    __shared__ unsigned s_posmask[TH];
    __shared__ int s_selfchg;

    const int tid = threadIdx.x;
    const int tx = tid & 31;
    const int ty = tid >> 5;                     // 0..7
    const int n = g_nwork[curPar];

    for (int w = blockIdx.x; w < n; w += gridDim.x) {
        __syncthreads();                         // smem reuse barrier
        const int b  = g_worklist[curPar][w];
        const int bx = b % NBX, by = b / NBX;
        const int c0 = bx * TW,  r0 = by * TH;

        if (tid == 0) s_selfchg = g_changed[prevPar][b];

        // ==== load raw x tile + halo ====
        #pragma unroll
        for (int k = 0; k < 3; k++) {
            int s = tid + k * 256;
            if (s < NSLOT) {
                int j = s / SW, i = s % SW;
                int r = r0 - 1 + j, c = c0 - 1 + i;
                bool ok = (r >= 0) && (r < HH) && (c >= 0) && (c < WW);
                xs[j][i] = ok ? xin[r * WW + c] : 0.0f;
            }
        }
        __syncthreads();

        // ==== per-cell possible upper bound ====
        float xx[2], gd[2];
        bool  pos[2];
        #pragma unroll
        for (int k = 0; k < 2; k++) {
            int jj = 1 + ty + k * 8, ii = 1 + tx;
            float M = xs[jj - 1][ii - 1];
            M = fmaxf(M, xs[jj - 1][ii    ]);
            M = fmaxf(M, xs[jj - 1][ii + 1]);
            M = fmaxf(M, xs[jj    ][ii - 1]);
            M = fmaxf(M, xs[jj    ][ii    ]);
            M = fmaxf(M, xs[jj    ][ii + 1]);
            M = fmaxf(M, xs[jj + 1][ii - 1]);
            M = fmaxf(M, xs[jj + 1][ii    ]);
            M = fmaxf(M, xs[jj + 1][ii + 1]);
            xx[k] = xs[jj][ii];
            int r = r0 + jj - 1, c = c0 + ii - 1;
            gd[k] = good[r * WW + c];
            pos[k] = __fsub_rn(__fmul_rn(M, gd[k]), xx[k]) > 0.05f;
            unsigned rowmask = __ballot_sync(0xffffffffu, pos[k]);
            if (tx == 0) s_posmask[ty + k * 8] = rowmask;
        }
        int any = __syncthreads_or((pos[0] || pos[1]) ? 1 : 0);

        if (!any) {
            // no update possible anywhere -> refresh buffer only if stale
            if (s_selfchg) {
                #pragma unroll
                for (int k = 0; k < 2; k++) {
                    int jj = 1 + ty + k * 8, ii = 1 + tx;
                    int r = r0 + jj - 1, c = c0 + ii - 1;
                    xout[r * WW + c] = xx[k];
                }
            }
            if (tid == 0) g_possible[b] = 0;     // changed[cur] pre-zeroed
            continue;
        }

        // ==== fill noised tile, cipher gated on pos-mask dilated by 1 px ====
        #pragma unroll
        for (int k = 0; k < 3; k++) {
            int s = tid + k * 256;
            bool sv = s < NSLOT;
            int ss = sv ? s : 0;
            int j = ss / SW, i = ss % SW;
            float x = sv ? xs[j][i] : 0.0f;
            unsigned rm = 0;
            #pragma unroll
            for (int dr = 0; dr < 3; dr++) {
                int cr = j - 2 + dr;
                if (cr >= 0 && cr < TH) rm |= s_posmask[cr];
            }
            unsigned long long rm2 = ((unsigned long long)rm) << 2;
            bool need = (((rm2 >> i) & 7ull) != 0ull) && (x > 0.0f);
            float y1 = 0.0f;
            if (__ballot_sync(0xffffffffu, need)) {
                int r = r0 - 1 + j, c = c0 - 1 + i;
                uint32_t p = (uint32_t)(min(max(r, 0), HH - 1) * WW +
                                        min(max(c, 0), WW - 1));
                float u = bits_to_uniform(pbits(k1a, k1b, p));
                float f = __fadd_rn(0.9999f, __fmul_rn(1e-4f, u));
                y1 = __fmul_rn(x, f);
            }
            if (sv) ys[j][i] = y1;
        }
        __syncthreads();

        // ==== maxpool + coin (cipher gated on pos) + write ====
        int chg = 0;
        #pragma unroll
        for (int k = 0; k < 2; k++) {
            int jj = 1 + ty + k * 8, ii = 1 + tx;
            float m = ys[jj - 1][ii - 1];
            m = fmaxf(m, ys[jj - 1][ii    ]);
            m = fmaxf(m, ys[jj - 1][ii + 1]);
            m = fmaxf(m, ys[jj    ][ii - 1]);
            m = fmaxf(m, ys[jj    ][ii    ]);
            m = fmaxf(m, ys[jj    ][ii + 1]);
            m = fmaxf(m, ys[jj + 1][ii - 1]);
            m = fmaxf(m, ys[jj + 1][ii    ]);
            m = fmaxf(m, ys[jj + 1][ii + 1]);

            int r = r0 + jj - 1, c = c0 + ii - 1;
            uint32_t p = (uint32_t)(r * WW + c);
            float y4 = 0.0f;
            if (__ballot_sync(0xffffffffu, pos[k])) {
                uint32_t bits = pbits(k2a, k2b, p);
                bool coin = ((bits >> 9) > 0x400000u);   // u > 0.5 strictly
                if (coin && m > 0.0f) y4 = __fmul_rn(m, gd[k]);
            }
            float d  = __fsub_rn(y4, xx[k]);
            float y5 = (d > 0.05f) ? y4 : 0.0f;
            float out = fmaxf(y5, xx[k]);
            xout[p] = out;
            chg |= (out != xx[k]) ? 1 : 0;
        }
        int anychg = __syncthreads_or(chg);
        if (tid == 0) {
            if (anychg) g_changed[curPar][b] = 1;
            g_possible[b] = 1;
        }
    }
}

// ---------------------------------------------------------------------------
// Host: per-iteration key schedule (fold_in + partitionable split), ping-pong.
// ---------------------------------------------------------------------------
extern "C" void kernel_launch(void* const* d_in, const int* in_sizes, int n_in,
                              void* d_out, int out_size) {
    const float* seed = (const float*)d_in[0];
    const float* hab  = (const float*)d_in[1];
    const float* good = (const float*)d_in[2];
    float* xout = (float*)d_out;

    float* scratch = nullptr;
    cudaGetSymbolAddress((void**)&scratch, g_scratch);

    init_kernel<<<(NPIX + 255) / 256, 256>>>(seed, hab, good, xout);

    for (int i = 0; i < 100; i++) {
        // fold_in(key(42)=(0,42), i) = cipher((0,42), (0,i))
        uint32_t f0, f1;
        tf2x32(0u, 42u, 0u, (uint32_t)i, f0, f1);
        // partitionable split: k1 = cipher(f,(0,0)), k2 = cipher(f,(0,1))
        uint32_t k1a, k1b, k2a, k2b;
        tf2x32(f0, f1, 0u, 0u, k1a, k1b);
        tf2x32(f0, f1, 0u, 1u, k2a, k2b);

        int prevPar = (i + 1) & 1, curPar = i & 1;
        const float* xin = (i & 1) ? scratch : xout;
        float*       xo  = (i & 1) ? xout    : scratch;

        flag_kernel<<<NB / 256, 256>>>(prevPar, curPar);
        step_kernel<<<STEP_GRID, 256>>>(xin, xo, good, k1a, k1b, k2a, k2b,
                                        prevPar, curPar);
    }
    // i = 99 (odd) wrote into xout -> final state lands in d_out
}